// round 6
// baseline (speedup 1.0000x reference)
#include <cuda_runtime.h>
#include <math.h>

// Problem constants (fixed by the dataset)
#define N_NODES 40000
#define N_EDGES 640000
#define DIM     128
#define OUTD    64
#define NGRAPH  64
#define SCAN_B  40            // ceil(40000/1024)

// ---------------- device scratch (no allocation allowed) ----------------
__device__ float g_t[N_NODES * DIM];     // GEMM output (pre-aggregation features)
__device__ float g_h[N_NODES * DIM];     // layer output (post relu)
__device__ int   g_cnt[N_NODES];         // in-degree counts
__device__ int   g_rowptr[N_NODES + 1];  // CSR row pointers (by dst)
__device__ int   g_cursor[N_NODES];      // scatter cursors
__device__ int   g_col[N_EDGES];         // CSR col (src) indices
__device__ float g_dinv[N_NODES];        // 1/sqrt(deg+1)
__device__ int   g_is64;                 // 1 if indices are int64, 0 if int32
// packed lookback state: high 32 bits = flag (0 invalid / 1 partial / 2 prefix),
// low 32 bits = value. Single 8-byte aligned word => atomic load/store.
__device__ volatile unsigned long long g_scan_pkt[SCAN_B];

// Uniform index load honoring detected dtype.
__device__ __forceinline__ int load_idx(const void* p, int i) {
    if (g_is64) return (int)((const long long*)p)[i];
    return ((const int*)p)[i];
}

// ---------------- init (+ dtype detection + scan-state reset) -------------
__global__ void init_kernel(const void* __restrict__ ei) {
    int i = blockIdx.x * blockDim.x + threadIdx.x;
    if (i == 0) {
        const long long* p = (const long long*)ei;
        int ok = 1;
        #pragma unroll
        for (int q = 0; q < 16; ++q) {
            long long v = p[q];
            if (v < 0 || v >= N_NODES) ok = 0;
        }
        g_is64 = ok;
    }
    if (i < SCAN_B) g_scan_pkt[i] = 0ull;
    if (i < N_NODES) g_cnt[i] = 0;
}

// ---------------- degree count (in-degree at dst) ----------------
__global__ __launch_bounds__(512) void count_kernel(const void* __restrict__ ei) {
    int e = blockIdx.x * blockDim.x + threadIdx.x;
    if (e < N_EDGES) {
        int dst = load_idx(ei, N_EDGES + e);
        atomicAdd(&g_cnt[dst], 1);
    }
}

// ---------------- single-pass decoupled-lookback exclusive scan -----------
// 40 blocks x 1024 threads; writes rowptr, cursor, dinv.
__global__ __launch_bounds__(1024) void scan_kernel() {
    __shared__ int wsum[32];
    __shared__ int s_off;
    int tid = threadIdx.x, lane = tid & 31, w = tid >> 5;
    int b = blockIdx.x;
    int i = b * 1024 + tid;
    int v = (i < N_NODES) ? g_cnt[i] : 0;

    // block-local inclusive scan
    int incl = v;
    #pragma unroll
    for (int off = 1; off < 32; off <<= 1) {
        int t = __shfl_up_sync(0xffffffffu, incl, off);
        if (lane >= off) incl += t;
    }
    if (lane == 31) wsum[w] = incl;
    __syncthreads();
    if (w == 0) {
        int s = wsum[lane];
        #pragma unroll
        for (int off = 1; off < 32; off <<= 1) {
            int t = __shfl_up_sync(0xffffffffu, s, off);
            if (lane >= off) s += t;
        }
        wsum[lane] = s;
    }
    __syncthreads();
    int pref = (w > 0) ? wsum[w - 1] : 0;
    int blkIncl = incl + pref;          // inclusive within block
    int blkTotal = wsum[31];            // block sum

    // decoupled lookback (thread 0); flag+value packed in ONE 64-bit word.
    if (tid == 0) {
        if (b == 0) {
            g_scan_pkt[0] = (2ull << 32) | (unsigned)blkTotal;
            s_off = 0;
        } else {
            g_scan_pkt[b] = (1ull << 32) | (unsigned)blkTotal;
            int sum = 0;
            int p = b - 1;
            while (p >= 0) {
                unsigned long long pkt;
                do { pkt = g_scan_pkt[p]; } while ((pkt >> 32) == 0ull);
                sum += (int)(unsigned)pkt;
                if ((pkt >> 32) == 2ull) break;
                --p;
            }
            g_scan_pkt[b] = (2ull << 32) | (unsigned)(sum + blkTotal);
            s_off = sum;
        }
    }
    __syncthreads();
    int offset = s_off;

    int inclTot = blkIncl + offset;
    if (i < N_NODES) {
        g_rowptr[i + 1] = inclTot;
        g_cursor[i] = inclTot - v;
        g_dinv[i] = rsqrtf((float)v + 1.0f);
        if (i == 0) g_rowptr[0] = 0;
    }
}

// ---------------- CSR fill: scatter src into per-dst slots ----------------
__global__ __launch_bounds__(512) void fill_kernel(const void* __restrict__ ei) {
    int e = blockIdx.x * blockDim.x + threadIdx.x;
    if (e < N_EDGES) {
        int src = load_idx(ei, e);
        int dst = load_idx(ei, N_EDGES + e);
        int pos = atomicAdd(&g_cursor[dst], 1);
        g_col[pos] = src;
    }
}

// ---------------- SGEMM: g_t = A(40000x128) @ W(128x128) ----------------
__global__ __launch_bounds__(128) void gemm_kernel(const float* __restrict__ Ain,
                                                   const float* __restrict__ W) {
    const float* A = Ain ? Ain : g_h;
    __shared__ float As[32][68];    // [k][m], padded
    __shared__ float Bs[32][128];   // [k][n]

    int tid  = threadIdx.x;
    int tcol = tid & 15;
    int trow = tid >> 4;
    int row0 = blockIdx.x * 64;

    float acc[8][8];
    #pragma unroll
    for (int i = 0; i < 8; ++i)
        #pragma unroll
        for (int j = 0; j < 8; ++j) acc[i][j] = 0.f;

    for (int kt = 0; kt < 4; ++kt) {
        {
            int m  = tid >> 1;
            int k0 = (tid & 1) * 16;
            const float* ap = &A[(row0 + m) * DIM + kt * 32 + k0];
            #pragma unroll
            for (int q = 0; q < 4; ++q) {
                float4 a = *(const float4*)(ap + q * 4);
                As[k0 + q * 4 + 0][m] = a.x;
                As[k0 + q * 4 + 1][m] = a.y;
                As[k0 + q * 4 + 2][m] = a.z;
                As[k0 + q * 4 + 3][m] = a.w;
            }
        }
        #pragma unroll
        for (int i = 0; i < 8; ++i) {
            int f  = tid + i * 128;
            int kk = f >> 5;
            int nn = (f & 31) * 4;
            *(float4*)&Bs[kk][nn] = *(const float4*)&W[(kt * 32 + kk) * DIM + nn];
        }
        __syncthreads();

        #pragma unroll
        for (int k = 0; k < 32; ++k) {
            float4 a0 = *(const float4*)&As[k][trow * 8];
            float4 a1 = *(const float4*)&As[k][trow * 8 + 4];
            float4 b0 = *(const float4*)&Bs[k][tcol * 8];
            float4 b1 = *(const float4*)&Bs[k][tcol * 8 + 4];
            float av[8] = {a0.x, a0.y, a0.z, a0.w, a1.x, a1.y, a1.z, a1.w};
            float bv[8] = {b0.x, b0.y, b0.z, b0.w, b1.x, b1.y, b1.z, b1.w};
            #pragma unroll
            for (int i = 0; i < 8; ++i)
                #pragma unroll
                for (int j = 0; j < 8; ++j)
                    acc[i][j] = fmaf(av[i], bv[j], acc[i][j]);
        }
        __syncthreads();
    }

    #pragma unroll
    for (int i = 0; i < 8; ++i) {
        int r = row0 + trow * 8 + i;
        float4 c0 = make_float4(acc[i][0], acc[i][1], acc[i][2], acc[i][3]);
        float4 c1 = make_float4(acc[i][4], acc[i][5], acc[i][6], acc[i][7]);
        *(float4*)&g_t[r * DIM + tcol * 8]     = c0;
        *(float4*)&g_t[r * DIM + tcol * 8 + 4] = c1;
    }
}

// ---------------- aggregation: warp-per-node, float4 gathers --------------
__global__ __launch_bounds__(256) void agg_kernel(const float* __restrict__ bias) {
    int warp = threadIdx.x >> 5;
    int lane = threadIdx.x & 31;
    int i = blockIdx.x * 8 + warp;

    float di = g_dinv[i];
    const float4 tself = *(const float4*)&g_t[(size_t)i * DIM + lane * 4];
    float4 acc;
    acc.x = di * di * tself.x;
    acc.y = di * di * tself.y;
    acc.z = di * di * tself.z;
    acc.w = di * di * tself.w;

    int s = g_rowptr[i], e = g_rowptr[i + 1];
    for (int base = s; base < e; base += 32) {
        int n = min(32, e - base);
        int c = 0; float wgt = 0.f;
        if (lane < n) {
            c = g_col[base + lane];
            wgt = g_dinv[c] * di;
        }
        #pragma unroll 8
        for (int j = 0; j < n; ++j) {
            int   cj = __shfl_sync(0xffffffffu, c, j);
            float wj = __shfl_sync(0xffffffffu, wgt, j);
            const float4 v = *(const float4*)&g_t[(size_t)cj * DIM + lane * 4];
            acc.x = fmaf(wj, v.x, acc.x);
            acc.y = fmaf(wj, v.y, acc.y);
            acc.z = fmaf(wj, v.z, acc.z);
            acc.w = fmaf(wj, v.w, acc.w);
        }
    }

    const float4 b4 = *(const float4*)&bias[lane * 4];
    float4 r;
    r.x = fmaxf(acc.x + b4.x, 0.f);
    r.y = fmaxf(acc.y + b4.y, 0.f);
    r.z = fmaxf(acc.z + b4.z, 0.f);
    r.w = fmaxf(acc.w + b4.w, 0.f);
    *(float4*)&g_h[(size_t)i * DIM + lane * 4] = r;
}

// ---------------- fused pool + linear + L2 normalize ----------------------
// One block per graph (128 threads). batch is sorted: binary-search range.
__global__ __launch_bounds__(128) void poolfinal_kernel(const void* __restrict__ batch,
                                                        const float* __restrict__ Wl,
                                                        const float* __restrict__ bl,
                                                        float* __restrict__ out) {
    int g = blockIdx.x;
    int tid = threadIdx.x;
    __shared__ int s_lo, s_hi;
    __shared__ float mean[DIM];
    __shared__ float outv[OUTD];
    __shared__ float red[OUTD];

    if (tid == 0 || tid == 1) {
        int target = g + tid;
        int lo = 0, hi = N_NODES;
        while (lo < hi) {
            int mid = (lo + hi) >> 1;
            if (load_idx(batch, mid) < target) lo = mid + 1;
            else hi = mid;
        }
        if (tid == 0) s_lo = lo; else s_hi = lo;
    }
    __syncthreads();
    int lo = s_lo, hi = s_hi;

    // coalesced column sum over contiguous node range
    float sum = 0.f;
    for (int n = lo; n < hi; ++n)
        sum += g_h[(size_t)n * DIM + tid];
    float cn = fmaxf((float)(hi - lo), 1.f);
    mean[tid] = sum / cn;
    __syncthreads();

    if (tid < OUTD) {
        float acc = bl[tid];
        #pragma unroll
        for (int h = 0; h < DIM; ++h)
            acc = fmaf(mean[h], Wl[h * OUTD + tid], acc);
        outv[tid] = acc;
        red[tid]  = acc * acc;
    }
    __syncthreads();
    for (int s = 32; s > 0; s >>= 1) {
        if (tid < s && tid + s < OUTD) red[tid] += red[tid + s];
        __syncthreads();
    }
    if (tid < OUTD) {
        float nrm = sqrtf(red[0]);
        out[g * OUTD + tid] = outv[tid] / fmaxf(nrm, 1e-12f);
    }
}

// ---------------- launch ----------------
extern "C" void kernel_launch(void* const* d_in, const int* in_sizes, int n_in,
                              void* d_out, int out_size) {
    const float* x     = (const float*)d_in[0];
    const float* W1    = (const float*)d_in[1];
    const float* b1    = (const float*)d_in[2];
    const float* W2    = (const float*)d_in[3];
    const float* b2    = (const float*)d_in[4];
    const float* Wl    = (const float*)d_in[5];
    const float* bl    = (const float*)d_in[6];
    const void*  ei    = d_in[7];
    const void*  batch = d_in[8];
    float* out = (float*)d_out;

    init_kernel<<<(N_NODES + 255) / 256, 256>>>(ei);
    count_kernel<<<(N_EDGES + 511) / 512, 512>>>(ei);
    scan_kernel<<<SCAN_B, 1024>>>();
    fill_kernel<<<(N_EDGES + 511) / 512, 512>>>(ei);

    // layer 1
    gemm_kernel<<<N_NODES / 64, 128>>>(x, W1);
    agg_kernel<<<N_NODES / 8, 256>>>(b1);
    // layer 2
    gemm_kernel<<<N_NODES / 64, 128>>>(nullptr, W2);
    agg_kernel<<<N_NODES / 8, 256>>>(b2);

    poolfinal_kernel<<<NGRAPH, 128>>>(batch, Wl, bl, out);
}